// round 16
// baseline (speedup 1.0000x reference)
#include <cuda_runtime.h>
#include <cstdint>

#define BB   64
#define LL   512
#define EE   128
#define CPG  256     // channels per kernel-size group
#define TCT  768     // total channels (3 groups)
#define OUTW 2304    // 3 segments * 768

// ---- scratch (static __device__: allocation-free) ----
__device__ __align__(16) float g_emb[BB * LL * EE];            // gathered embeddings
__device__ __align__(16) float g_wT[(3 + 5 + 7) * EE * CPG];   // transposed weights [k][e][c]
__device__ int g_segpos[BB][3];                                // first occurrence of tokens 1,2,3

static const int W3SZ = 3 * EE * CPG;   // 98304
static const int W5SZ = 5 * EE * CPG;   // 163840

// shared layout: As (70 x 132 floats) | Ws double buffer (2 x 7*4*128 floats)
#define APAD     132
#define WS_OFF   (70 * APAD)                        // 9240 floats
#define WBUF     (7 * 4 * 128)                      // 3584 floats per buffer (K=7 max)
#define SMEM_TOT ((WS_OFF + 2 * WBUF) * 4)          // 65632 bytes -> 3 CTAs/SM

// --------------------------------------------------------------------------
__device__ __forceinline__ uint32_t smem_u32(const void* p) {
    uint32_t a;
    asm("{ .reg .u64 t; cvta.to.shared.u64 t, %1; cvt.u32.u64 %0, t; }" : "=r"(a) : "l"(p));
    return a;
}
__device__ __forceinline__ void cp_async16(uint32_t dst, const void* src) {
    asm volatile("cp.async.cg.shared.global [%0], [%1], 16;" :: "r"(dst), "l"(src));
}
#define CP_COMMIT() asm volatile("cp.async.commit_group;" ::: "memory")
#define CP_WAIT0()  asm volatile("cp.async.wait_group 0;" ::: "memory")

// --------------------------------------------------------------------------
// prep: segment boundaries + zero output (atomicMax base)
// --------------------------------------------------------------------------
__global__ void prep_kernel(const int* __restrict__ inp, float* __restrict__ out) {
    __shared__ int fpos[3];
    const int b = blockIdx.x;
    const int tid = threadIdx.x;
    if (tid < 3) fpos[tid] = LL - 1;
    __syncthreads();
    for (int l = tid; l < LL; l += blockDim.x) {
        int tok = inp[b * LL + l];
        if (tok >= 1 && tok <= 3) atomicMin(&fpos[tok - 1], l);
    }
    __syncthreads();
    if (tid < 3) g_segpos[b][tid] = fpos[tid];
    for (int i = tid; i < OUTW; i += blockDim.x) out[b * OUTW + i] = 0.0f;
}

// --------------------------------------------------------------------------
// gather: emb_weight[inputs] -> g_emb  (coalesced float4, one streaming pass)
// --------------------------------------------------------------------------
__global__ void gather_kernel(const int* __restrict__ inp, const float* __restrict__ emb) {
    int idx = blockIdx.x * blockDim.x + threadIdx.x;   // over B*L*32 float4s
    int row = idx >> 5;
    int q = idx & 31;
    int tok = inp[row];
    reinterpret_cast<float4*>(g_emb)[idx] =
        reinterpret_cast<const float4*>(emb + (size_t)tok * EE)[q];
}

// --------------------------------------------------------------------------
// merged weight transpose: all three groups in one launch
// --------------------------------------------------------------------------
__global__ void wtrans_all(const float* __restrict__ w3,
                           const float* __restrict__ w5,
                           const float* __restrict__ w7) {
    int r = blockIdx.x;            // 0 .. 15*128-1
    const float* src;
    int KE, dstoff;
    if (r < 3 * EE)       { src = w3; KE = 3 * EE; dstoff = 0; }
    else if (r < 8 * EE)  { src = w5; KE = 5 * EE; dstoff = W3SZ;        r -= 3 * EE; }
    else                  { src = w7; KE = 7 * EE; dstoff = W3SZ + W5SZ; r -= 8 * EE; }
    int c = threadIdx.x;
    g_wT[dstoff + r * CPG + c] = src[c * KE + r];
}

// --------------------------------------------------------------------------
// conv body: R10 mapping (tx=tid&15 -> 8 channels, ty=tid>>4 -> 4 L-positions)
// weight chunks of 4 e's, cp.async double-buffered (load ch+1 during compute ch)
// --------------------------------------------------------------------------
template <int K>
__device__ __forceinline__ void conv_body(float* smem,
                                          const float* __restrict__ bias,
                                          float* __restrict__ out,
                                          int woff, int gbase,
                                          int lbase, int cbase, int b) {
    constexpr int LO = (K - 1) / 2;
    constexpr int AROWS = 64 + K - 1;
    float* As = smem;
    float* Ws = smem + WS_OFF;
    const float* wT = g_wT + woff;

    const int tid = threadIdx.x;
    const int tx = tid & 15;
    const int ty = tid >> 4;
    const int ty4 = ty * 4;

    const int p1 = g_segpos[b][0], p2 = g_segpos[b][1], p3 = g_segpos[b][2];
    if (lbase > p3) return;              // tile never pooled

    const uint32_t ws_u32 = smem_u32(Ws);

    // --- stage embedding tile from pre-gathered g_emb (halo, zero-padded) ---
    const float4* embr = reinterpret_cast<const float4*>(g_emb + (size_t)b * LL * EE);
    for (int i = tid; i < AROWS * 32; i += 256) {
        int r = i >> 5, q = i & 31;
        int gl = lbase - LO + r;
        float4 v = make_float4(0.f, 0.f, 0.f, 0.f);
        if (gl >= 0 && gl < LL) v = embr[gl * 32 + q];
        *reinterpret_cast<float4*>(&As[r * APAD + q * 4]) = v;
    }

    // --- prologue: async-load weight chunk 0 into buffer 0 ---
    for (int i = tid; i < K * 4 * 32; i += 256) {
        int r = i >> 5, q = i & 31;          // r = k*4 + e4
        int k = r >> 2, e4 = r & 3;
        cp_async16(ws_u32 + (uint32_t)(r * 128 + q * 4) * 4,
                   &wT[(size_t)(k * EE + e4) * CPG + cbase + q * 4]);
    }
    CP_COMMIT();

    unsigned long long acc[4][4];
#pragma unroll
    for (int mi = 0; mi < 4; mi++)
#pragma unroll
        for (int j = 0; j < 4; j++) acc[mi][j] = 0ull;

    for (int ch = 0; ch < 32; ch++) {
        CP_WAIT0();                          // chunk ch resident (issued one phase ago)
        __syncthreads();                     // visible to all; prev compute done

        if (ch < 31) {                       // async-load chunk ch+1 into other buffer
            uint32_t dstbuf = ws_u32 + (uint32_t)(((ch + 1) & 1) * WBUF) * 4;
            int en = (ch + 1) * 4;
            for (int i = tid; i < K * 4 * 32; i += 256) {
                int r = i >> 5, q = i & 31;
                int k = r >> 2, e4 = r & 3;
                cp_async16(dstbuf + (uint32_t)(r * 128 + q * 4) * 4,
                           &wT[(size_t)(k * EE + en + e4) * CPG + cbase + q * 4]);
            }
            CP_COMMIT();
        }

        const float* Wb = Ws + (ch & 1) * WBUF;
        const int e0 = ch * 4;
#pragma unroll
        for (int e4 = 0; e4 < 4; e4++) {
            unsigned long long a2[K + 3];
#pragma unroll
            for (int rr = 0; rr < K + 3; rr++) {
                float av = As[(ty4 + rr) * APAD + e0 + e4];
                asm("mov.b64 %0, {%1, %1};" : "=l"(a2[rr]) : "f"(av));
            }
#pragma unroll
            for (int k = 0; k < K; k++) {
                const ulonglong2* wrow =
                    reinterpret_cast<const ulonglong2*>(&Wb[(k * 4 + e4) * 128]);
                ulonglong2 w01 = wrow[tx];        // channel pairs 4tx, 4tx+2
                ulonglong2 w23 = wrow[tx + 16];   // channel pairs 64+4tx, 64+4tx+2
                unsigned long long b2[4] = {w01.x, w01.y, w23.x, w23.y};
#pragma unroll
                for (int mi = 0; mi < 4; mi++)
#pragma unroll
                    for (int j = 0; j < 4; j++)
                        asm("fma.rn.f32x2 %0, %1, %2, %0;"
                            : "+l"(acc[mi][j])
                            : "l"(a2[mi + k]), "l"(b2[j]));
            }
        }
    }

    // --- epilogue: bias + relu, segmented max into smem, global atomicMax ---
    __syncthreads();
    int* segm = reinterpret_cast<int*>(smem);
    for (int i = tid; i < 3 * 128; i += 256) segm[i] = 0;

    int slo[3] = {0, p1, p2};
    int shi[3] = {p1, p2, p3};
    __syncthreads();

#pragma unroll
    for (int j = 0; j < 4; j++) {
        int cl0 = ((j >> 1) << 6) + 4 * tx + ((j & 1) << 1);
        float b0 = bias[cbase + cl0], b1 = bias[cbase + cl0 + 1];
        float vx[4], vy[4];
#pragma unroll
        for (int mi = 0; mi < 4; mi++) {
            float x, y;
            asm("mov.b64 {%0, %1}, %2;" : "=f"(x), "=f"(y) : "l"(acc[mi][j]));
            vx[mi] = fmaxf(x + b0, 0.0f);
            vy[mi] = fmaxf(y + b1, 0.0f);
        }
#pragma unroll
        for (int t = 0; t < 3; t++) {
            float mx = -1.0f, my = -1.0f;
            bool any = false;
#pragma unroll
            for (int mi = 0; mi < 4; mi++) {
                int l = lbase + ty4 + mi;
                bool in = (l >= slo[t] && l <= shi[t]);
                if (in) { mx = fmaxf(mx, vx[mi]); my = fmaxf(my, vy[mi]); any = true; }
            }
            if (any) {
                if (mx > 0.0f) atomicMax(&segm[t * 128 + cl0], __float_as_int(mx));
                if (my > 0.0f) atomicMax(&segm[t * 128 + cl0 + 1], __float_as_int(my));
            }
        }
    }
    __syncthreads();
    for (int i = tid; i < 3 * 128; i += 256) {
        int t = i >> 7, c = i & 127;
        if (segm[i] != 0)
            atomicMax(reinterpret_cast<int*>(&out[(size_t)b * OUTW + t * TCT + gbase + cbase + c]),
                      segm[i]);
    }
}

// --------------------------------------------------------------------------
// merged conv: grid (8 Ltiles, 2 Ctiles, 192 = b*3 + g), one launch
// --------------------------------------------------------------------------
__global__ void __launch_bounds__(256, 3) conv_all(const float* __restrict__ b3,
                                                   const float* __restrict__ b5,
                                                   const float* __restrict__ b7,
                                                   float* __restrict__ out) {
    extern __shared__ float smem[];
    const int lbase = blockIdx.x * 64;
    const int cbase = blockIdx.y * 128;
    const int g = blockIdx.z % 3;
    const int b = blockIdx.z / 3;

    if (g == 0)      conv_body<3>(smem, b3, out, 0,           0,   lbase, cbase, b);
    else if (g == 1) conv_body<5>(smem, b5, out, W3SZ,        256, lbase, cbase, b);
    else             conv_body<7>(smem, b7, out, W3SZ + W5SZ, 512, lbase, cbase, b);
}

// --------------------------------------------------------------------------
extern "C" void kernel_launch(void* const* d_in, const int* in_sizes, int n_in,
                              void* d_out, int out_size) {
    // map by element count; positional fallback
    const int* inp = nullptr;
    const float *emb = nullptr, *w3 = nullptr, *w5 = nullptr, *w7 = nullptr;
    const float* biases[3] = {nullptr, nullptr, nullptr};
    int nb = 0;
    for (int i = 0; i < n_in; i++) {
        switch (in_sizes[i]) {
            case 32768:   inp = (const int*)d_in[i];   break;
            case 6400000: emb = (const float*)d_in[i]; break;
            case 98304:   w3 = (const float*)d_in[i];  break;
            case 163840:  w5 = (const float*)d_in[i];  break;
            case 229376:  w7 = (const float*)d_in[i];  break;
            case 256:     if (nb < 3) biases[nb++] = (const float*)d_in[i]; break;
            default: break;
        }
    }
    if (!inp || !emb || !w3 || !w5 || !w7 || nb != 3) {
        inp = (const int*)d_in[0];
        emb = (const float*)d_in[1];
        w3 = (const float*)d_in[2];  biases[0] = (const float*)d_in[3];
        w5 = (const float*)d_in[4];  biases[1] = (const float*)d_in[5];
        w7 = (const float*)d_in[6];  biases[2] = (const float*)d_in[7];
    }
    float* out = (float*)d_out;
    (void)out_size;

    cudaFuncSetAttribute(conv_all, cudaFuncAttributeMaxDynamicSharedMemorySize, SMEM_TOT);

    prep_kernel<<<BB, 256>>>(inp, out);
    gather_kernel<<<(BB * LL * 32) / 256, 256>>>(inp, emb);
    wtrans_all<<<15 * EE, 256>>>(w3, w5, w7);

    conv_all<<<dim3(8, 2, 192), 256, SMEM_TOT>>>(biases[0], biases[1], biases[2], out);
}